// round 7
// baseline (speedup 1.0000x reference)
#include <cuda_runtime.h>
#include <cstdint>

// DynamicKVCache update: out = [concat(cache_k, key, dim=1), concat(cache_v, value, dim=1)]
// Shapes: cache [8, 4096, 32, 128] f32, new [8, 1, 32, 128] f32.
//
// Streaming copy at the B300 HBM mixed-stream ceiling (~88% DRAM-active,
// ~7.0 TB/s, invariant across MLP/occ/chunk configs). This round probes
// 256-bit (v8.f32) global loads/stores (sm_100+): half the LDG/STG count,
// 1024B contiguous per warp per instruction -> coarser DRAM burst stream.
// Layout: 256 threads x 4 x 32B = 32KB chunk (2048 float4), cache region =
// 2048 exact chunks/batch, appended slot = half-chunk tail block.

static constexpr long long CACHE_F4  = 4096LL * 4096 / 4;    // 4,194,304 float4
static constexpr long long NEW_F4    = 4096LL / 4;           // 1,024 float4
static constexpr long long BATCH_F4  = CACHE_F4 + NEW_F4;    // 4,195,328
static constexpr long long TENSOR_F4 = 8LL * BATCH_F4;
static constexpr int THREADS   = 256;
static constexpr int CHUNK_F4  = 2048;                       // float4 per full chunk (32KB)
static constexpr int CACHE_CHUNKS = (int)(CACHE_F4 / CHUNK_F4); // 2048, exact
static constexpr int BLOCKS_X  = CACHE_CHUNKS + 1;           // +1 tail (new slot)
static constexpr int STEP_F4   = THREADS * 2;                // 512 float4 per v8 step

struct v8 { float a0,a1,a2,a3,a4,a5,a6,a7; };

__device__ __forceinline__ v8 ldg256_cs(const float* p) {
    v8 r;
    asm volatile("ld.global.cs.v8.f32 {%0,%1,%2,%3,%4,%5,%6,%7}, [%8];"
                 : "=f"(r.a0), "=f"(r.a1), "=f"(r.a2), "=f"(r.a3),
                   "=f"(r.a4), "=f"(r.a5), "=f"(r.a6), "=f"(r.a7)
                 : "l"(p));
    return r;
}

__device__ __forceinline__ void stg256_cs(float* p, const v8& r) {
    asm volatile("st.global.cs.v8.f32 [%0], {%1,%2,%3,%4,%5,%6,%7,%8};"
                 :: "l"(p),
                    "f"(r.a0), "f"(r.a1), "f"(r.a2), "f"(r.a3),
                    "f"(r.a4), "f"(r.a5), "f"(r.a6), "f"(r.a7)
                 : "memory");
}

__global__ __launch_bounds__(THREADS)
void kvcache_concat_kernel(const float* __restrict__ cache_k,
                           const float* __restrict__ cache_v,
                           const float* __restrict__ key,
                           const float* __restrict__ value,
                           float* __restrict__ out)
{
    const int chunk = blockIdx.x;    // [0, 2049)
    const int b     = blockIdx.y;    // batch
    const int t     = blockIdx.z;    // 0 = k, 1 = v

    // All offsets below in float4 units * 4 = float units.
    const long long out_base_f = 4LL * ((long long)t * TENSOR_F4
                                      + (long long)b * BATCH_F4
                                      + (long long)chunk * CHUNK_F4);
    const int tid = threadIdx.x;
    const long long lane_f = (long long)tid * 8;   // 8 floats = 32B per lane

    const float* __restrict__ cache = t ? cache_v : cache_k;
    const float* __restrict__ nw    = t ? value   : key;

    if (chunk < CACHE_CHUNKS) {
        const float* __restrict__ src =
            cache + 4LL * ((long long)b * CACHE_F4 + (long long)chunk * CHUNK_F4);
        // 4 independent 32B loads per thread (covers 2048 f4 chunk), then 4 stores.
        v8 v0 = ldg256_cs(src + lane_f);
        v8 v1 = ldg256_cs(src + lane_f + 4LL * STEP_F4);
        v8 v2 = ldg256_cs(src + lane_f + 8LL * STEP_F4);
        v8 v3 = ldg256_cs(src + lane_f + 12LL * STEP_F4);
        stg256_cs(out + out_base_f + lane_f,                 v0);
        stg256_cs(out + out_base_f + lane_f + 4LL * STEP_F4, v1);
        stg256_cs(out + out_base_f + lane_f + 8LL * STEP_F4, v2);
        stg256_cs(out + out_base_f + lane_f + 12LL* STEP_F4, v3);
    } else {
        // Appended slot: 1024 float4 = 4096 floats -> 2 v8 steps.
        const float* __restrict__ src = nw + 4LL * (long long)b * NEW_F4;
        v8 v0 = ldg256_cs(src + lane_f);
        v8 v1 = ldg256_cs(src + lane_f + 4LL * STEP_F4);
        stg256_cs(out + out_base_f + lane_f,                 v0);
        stg256_cs(out + out_base_f + lane_f + 4LL * STEP_F4, v1);
    }
}

extern "C" void kernel_launch(void* const* d_in, const int* in_sizes, int n_in,
                              void* d_out, int out_size)
{
    const float* cache_k = (const float*)d_in[0];
    const float* cache_v = (const float*)d_in[1];
    const float* key     = (const float*)d_in[2];
    const float* value   = (const float*)d_in[3];
    float* out = (float*)d_out;

    dim3 grid(BLOCKS_X, 8, 2);
    kvcache_concat_kernel<<<grid, THREADS>>>(cache_k, cache_v, key, value, out);
}

// round 8
// speedup vs baseline: 1.0041x; 1.0041x over previous
#include <cuda_runtime.h>

// DynamicKVCache update: out = [concat(cache_k, key, dim=1), concat(cache_v, value, dim=1)]
// Shapes: cache [8, 4096, 32, 128] f32, new [8, 1, 32, 128] f32.
//
// FINAL — pinned at the B300 HBM mixed-stream roofline.
// Evidence: kernel time 299.3-301.7us and DRAM-active 87.5-88.2% invariant
// across MLP_p1 {1,4,8}, occupancy {60-80%}, chunk {16,32}KB, and request
// width {16B,32B} probes. Irreducible traffic = 2.148 GB (read both caches +
// new slots once, write full output once); ~7.0 TB/s achieved = ~88% of
// 8 TB/s spec. Residual is DRAM R/W bus turnaround — not kernel-addressable.
//
// Config: 256 threads x 8 float4 (32KB chunk), evict-first (.cs) loads and
// stores, cache region = 2048 exact chunks/batch, appended key/value slot =
// one half-chunk tail block per batch (uniform per-block branch).
// Grid = (2049, 8 batches, 2 tensors).

static constexpr long long CACHE_F4  = 4096LL * 4096 / 4;    // 4,194,304
static constexpr long long NEW_F4    = 4096LL / 4;           // 1,024
static constexpr long long BATCH_F4  = CACHE_F4 + NEW_F4;    // 4,195,328
static constexpr long long TENSOR_F4 = 8LL * BATCH_F4;
static constexpr int THREADS   = 256;
static constexpr int PER_TH    = 8;                          // float4 per thread (full chunk)
static constexpr int CHUNK_F4  = THREADS * PER_TH;           // 2048
static constexpr int CACHE_CHUNKS = (int)(CACHE_F4 / CHUNK_F4); // 2048, exact
static constexpr int BLOCKS_X  = CACHE_CHUNKS + 1;           // +1 tail (new slot, 1024 f4)

__global__ __launch_bounds__(THREADS)
void kvcache_concat_kernel(const float4* __restrict__ cache_k,
                           const float4* __restrict__ cache_v,
                           const float4* __restrict__ key,
                           const float4* __restrict__ value,
                           float4* __restrict__ out)
{
    const int chunk = blockIdx.x;    // [0, 2049)
    const int b     = blockIdx.y;    // batch
    const int t     = blockIdx.z;    // 0 = k, 1 = v

    const long long out_base = (long long)t * TENSOR_F4
                             + (long long)b * BATCH_F4
                             + (long long)chunk * CHUNK_F4;
    const int tid = threadIdx.x;

    const float4* __restrict__ cache = t ? cache_v : cache_k;
    const float4* __restrict__ nw    = t ? value   : key;

    if (chunk < CACHE_CHUNKS) {
        // Full 32KB chunk: 8 independent coalesced LDG.128, then 8 STG.128.
        const float4* __restrict__ src =
            cache + (long long)b * CACHE_F4 + (long long)chunk * CHUNK_F4;
        float4 v[PER_TH];
#pragma unroll
        for (int j = 0; j < PER_TH; j++)
            v[j] = __ldcs(src + tid + j * THREADS);
#pragma unroll
        for (int j = 0; j < PER_TH; j++)
            __stcs(out + out_base + tid + j * THREADS, v[j]);
    } else {
        // Appended slot: 1024 float4 (half chunk), uniform per-block path.
        const float4* __restrict__ src = nw + (long long)b * NEW_F4;
        float4 v[4];
#pragma unroll
        for (int j = 0; j < 4; j++)
            v[j] = __ldcs(src + tid + j * THREADS);
#pragma unroll
        for (int j = 0; j < 4; j++)
            __stcs(out + out_base + tid + j * THREADS, v[j]);
    }
}

extern "C" void kernel_launch(void* const* d_in, const int* in_sizes, int n_in,
                              void* d_out, int out_size)
{
    const float4* cache_k = (const float4*)d_in[0];
    const float4* cache_v = (const float4*)d_in[1];
    const float4* key     = (const float4*)d_in[2];
    const float4* value   = (const float4*)d_in[3];
    float4* out = (float4*)d_out;

    dim3 grid(BLOCKS_X, 8, 2);
    kvcache_concat_kernel<<<grid, THREADS>>>(cache_k, cache_v, key, value, out);
}

// round 9
// speedup vs baseline: 1.0089x; 1.0048x over previous
#include <cuda_runtime.h>

// DynamicKVCache update: out = [concat(cache_k, key, dim=1), concat(cache_v, value, dim=1)]
// Shapes: cache [8, 4096, 32, 128] f32, new [8, 1, 32, 128] f32.
//
// FINAL — pinned at the B300 HBM mixed-stream roofline (converged, R2-R8).
// Evidence: kernel time 299.0-301.7us and DRAM-active 87.5-88.3% invariant
// across MLP_p1 {1,4,8}, occupancy {60-80%}, chunk {16,32}KB, and request
// width {16B,32B} probes. Irreducible traffic = 2.148 GB (read both caches +
// new slots once, write full output once); ~7.0 TB/s achieved = ~88% of
// 8 TB/s spec. Residual vs spec is DRAM R/W bus turnaround on a 50/50
// mixed stream — not kernel-addressable (LDG/TMA/LTS share one chip cap).
//
// Config: 256 threads x 8 float4 (32KB chunk), evict-first (.cs) loads and
// stores, cache region = 2048 exact chunks/batch, appended key/value slot =
// one half-chunk tail block per batch (uniform per-block branch, zero
// per-thread divergence). Grid = (2049, 8 batches, 2 tensors).

static constexpr long long CACHE_F4  = 4096LL * 4096 / 4;    // 4,194,304
static constexpr long long NEW_F4    = 4096LL / 4;           // 1,024
static constexpr long long BATCH_F4  = CACHE_F4 + NEW_F4;    // 4,195,328
static constexpr long long TENSOR_F4 = 8LL * BATCH_F4;
static constexpr int THREADS   = 256;
static constexpr int PER_TH    = 8;                          // float4 per thread (full chunk)
static constexpr int CHUNK_F4  = THREADS * PER_TH;           // 2048
static constexpr int CACHE_CHUNKS = (int)(CACHE_F4 / CHUNK_F4); // 2048, exact
static constexpr int BLOCKS_X  = CACHE_CHUNKS + 1;           // +1 tail (new slot, 1024 f4)

__global__ __launch_bounds__(THREADS)
void kvcache_concat_kernel(const float4* __restrict__ cache_k,
                           const float4* __restrict__ cache_v,
                           const float4* __restrict__ key,
                           const float4* __restrict__ value,
                           float4* __restrict__ out)
{
    const int chunk = blockIdx.x;    // [0, 2049)
    const int b     = blockIdx.y;    // batch
    const int t     = blockIdx.z;    // 0 = k, 1 = v

    const long long out_base = (long long)t * TENSOR_F4
                             + (long long)b * BATCH_F4
                             + (long long)chunk * CHUNK_F4;
    const int tid = threadIdx.x;

    const float4* __restrict__ cache = t ? cache_v : cache_k;
    const float4* __restrict__ nw    = t ? value   : key;

    if (chunk < CACHE_CHUNKS) {
        // Full 32KB chunk: 8 independent coalesced LDG.128, then 8 STG.128.
        const float4* __restrict__ src =
            cache + (long long)b * CACHE_F4 + (long long)chunk * CHUNK_F4;
        float4 v[PER_TH];
#pragma unroll
        for (int j = 0; j < PER_TH; j++)
            v[j] = __ldcs(src + tid + j * THREADS);
#pragma unroll
        for (int j = 0; j < PER_TH; j++)
            __stcs(out + out_base + tid + j * THREADS, v[j]);
    } else {
        // Appended slot: 1024 float4 (half chunk), uniform per-block path.
        const float4* __restrict__ src = nw + (long long)b * NEW_F4;
        float4 v[4];
#pragma unroll
        for (int j = 0; j < 4; j++)
            v[j] = __ldcs(src + tid + j * THREADS);
#pragma unroll
        for (int j = 0; j < 4; j++)
            __stcs(out + out_base + tid + j * THREADS, v[j]);
    }
}

extern "C" void kernel_launch(void* const* d_in, const int* in_sizes, int n_in,
                              void* d_out, int out_size)
{
    const float4* cache_k = (const float4*)d_in[0];
    const float4* cache_v = (const float4*)d_in[1];
    const float4* key     = (const float4*)d_in[2];
    const float4* value   = (const float4*)d_in[3];
    float4* out = (float4*)d_out;

    dim3 grid(BLOCKS_X, 8, 2);
    kvcache_concat_kernel<<<grid, THREADS>>>(cache_k, cache_v, key, value, out);
}